// round 8
// baseline (speedup 1.0000x reference)
#include <cuda_runtime.h>
#include <cstdint>

// Problem constants.
#define NSLICE 32      // B*KI = 8*4
#define NN     2048    // nodes per slice
#define IW     32
#define OW     32

// exp(-sq/2) = exp2(C1 * sq), C1 = -1/(2 ln 2)
#define C1   (-0.7213475204444817f)
#define M2C1 ( 1.4426950408889634f)   // -2*C1
#define WLSCALE    4096.0f
#define INV_WLSCALE (1.0f / 4096.0f)

// Scratch (device globals: allocation-free contract).
__device__ float g_inv_d2[NSLICE * NN];
// wl as packed fp16x2 (scaled by WLSCALE), B-fragment layout:
// [slice][chunk16(128)][lane(32)][nb(4)][h(2)] -> 8 contiguous u32 per lane.
__device__ unsigned g_wlh[(size_t)NSLICE * 128 * 32 * 8];

// ---------------------------------------------------------------------------
// PTX helpers
// ---------------------------------------------------------------------------
__device__ __forceinline__ float ex2f(float x) {
    float y; asm("ex2.approx.f32 %0, %1;" : "=f"(y) : "f"(x)); return y;
}
__device__ __forceinline__ unsigned pack_f16(float lo, float hi) {
    unsigned d;
    asm("cvt.rn.f16x2.f32 %0, %1, %2;" : "=r"(d) : "f"(hi), "f"(lo));
    return d;
}
// product MMA: C += A(16x16) * B(16x8), fp16 -> fp32
__device__ __forceinline__ void mma_f16(float* c, unsigned a0, unsigned a1,
                                        unsigned a2, unsigned a3,
                                        unsigned b0, unsigned b1) {
    asm volatile(
        "mma.sync.aligned.m16n8k16.row.col.f32.f16.f16.f32 "
        "{%0,%1,%2,%3}, {%4,%5,%6,%7}, {%8,%9}, {%0,%1,%2,%3};"
        : "+f"(c[0]), "+f"(c[1]), "+f"(c[2]), "+f"(c[3])
        : "r"(a0), "r"(a1), "r"(a2), "r"(a3), "r"(b0), "r"(b1));
}
__device__ __forceinline__ void cp_async16(uint32_t dst, const void* src) {
    asm volatile("cp.async.cg.shared.global [%0], [%1], 16;" :: "r"(dst), "l"(src));
}

// ---------------------------------------------------------------------------
// Pass A (fused): degrees with FULL-FP32 distance args (no tensor op in the
// degree sum -> no common-mode d_i error), then wl epilogue in scaled-fp16
// B-fragment order. 512 blocks x 256 thr; warp owns 16 rows.
// ---------------------------------------------------------------------------
__global__ void __launch_bounds__(256) deg_wl_kernel(
    const float* __restrict__ pos, const float* __restrict__ w,
    const float* __restrict__ lin_w, float* __restrict__ inv_d2,
    unsigned* __restrict__ wlh) {
    __shared__ float4 ps[NN];        // 32 KB: (x, y, z, C1*|p|^2)
    __shared__ float  s_inv[128];
    __shared__ float  lw[OW * 33];   // lin_w padded

    int slice = blockIdx.x >> 4;
    int iblk  = blockIdx.x & 15;
    const float* p = pos + (size_t)slice * NN * 3;
    int tid = threadIdx.x;

    for (int t = tid; t < OW * IW; t += 256)
        lw[(t >> 5) * 33 + (t & 31)] = lin_w[t];

    for (int n = tid; n < NN; n += 256) {
        float x = p[3 * n + 0], y = p[3 * n + 1], z = p[3 * n + 2];
        ps[n] = make_float4(x, y, z, C1 * (x * x + y * y + z * z));
    }

    int warp = tid >> 5;
    int lane = tid & 31;
    int g = lane >> 2, tg = lane & 3;
    int row_lo = iblk * 128 + warp * 16 + g;
    int row_hi = row_lo + 8;

    float qxl, qyl, qzl, csl, qxh, qyh, qzh, csh;
    {
        float x = p[3 * row_lo], y = p[3 * row_lo + 1], z = p[3 * row_lo + 2];
        csl = C1 * (x * x + y * y + z * z);
        qxl = M2C1 * x; qyl = M2C1 * y; qzl = M2C1 * z;
        x = p[3 * row_hi]; y = p[3 * row_hi + 1]; z = p[3 * row_hi + 2];
        csh = C1 * (x * x + y * y + z * z);
        qxh = M2C1 * x; qyh = M2C1 * y; qzh = M2C1 * z;
    }
    __syncthreads();

    // Degree loop: each thread covers j = cc*16 + {2tg, 2tg+1, 2tg+8, 2tg+9},
    // both rows; lanes with same g cover all 16 j of the chunk.
    float al0 = 0.0f, al1 = 0.0f, ah0 = 0.0f, ah1 = 0.0f;
#pragma unroll 2
    for (int cc = 0; cc < NN / 16; cc++) {
        int j0 = cc * 16 + 2 * tg;
        float4 pj0 = ps[j0];
        float4 pj1 = ps[j0 + 1];
        float4 pj2 = ps[j0 + 8];
        float4 pj3 = ps[j0 + 9];

        float tl0 = csl + pj0.w;
        tl0 = fmaf(qxl, pj0.x, tl0); tl0 = fmaf(qyl, pj0.y, tl0); tl0 = fmaf(qzl, pj0.z, tl0);
        float tl1 = csl + pj1.w;
        tl1 = fmaf(qxl, pj1.x, tl1); tl1 = fmaf(qyl, pj1.y, tl1); tl1 = fmaf(qzl, pj1.z, tl1);
        float tl2 = csl + pj2.w;
        tl2 = fmaf(qxl, pj2.x, tl2); tl2 = fmaf(qyl, pj2.y, tl2); tl2 = fmaf(qzl, pj2.z, tl2);
        float tl3 = csl + pj3.w;
        tl3 = fmaf(qxl, pj3.x, tl3); tl3 = fmaf(qyl, pj3.y, tl3); tl3 = fmaf(qzl, pj3.z, tl3);

        float th0 = csh + pj0.w;
        th0 = fmaf(qxh, pj0.x, th0); th0 = fmaf(qyh, pj0.y, th0); th0 = fmaf(qzh, pj0.z, th0);
        float th1 = csh + pj1.w;
        th1 = fmaf(qxh, pj1.x, th1); th1 = fmaf(qyh, pj1.y, th1); th1 = fmaf(qzh, pj1.z, th1);
        float th2 = csh + pj2.w;
        th2 = fmaf(qxh, pj2.x, th2); th2 = fmaf(qyh, pj2.y, th2); th2 = fmaf(qzh, pj2.z, th2);
        float th3 = csh + pj3.w;
        th3 = fmaf(qxh, pj3.x, th3); th3 = fmaf(qyh, pj3.y, th3); th3 = fmaf(qzh, pj3.z, th3);

        al0 += ex2f(tl0); al1 += ex2f(tl1); al0 += ex2f(tl2); al1 += ex2f(tl3);
        ah0 += ex2f(th0); ah1 += ex2f(th1); ah0 += ex2f(th2); ah1 += ex2f(th3);
    }
    float accl = al0 + al1;
    float acch = ah0 + ah1;
    // reduce over the 4 threads sharing g (tg = 0..3)
    accl += __shfl_xor_sync(0xffffffffu, accl, 1);
    accl += __shfl_xor_sync(0xffffffffu, accl, 2);
    acch += __shfl_xor_sync(0xffffffffu, acch, 1);
    acch += __shfl_xor_sync(0xffffffffu, acch, 2);
    if (tg == 0) {
        float invl = 1.0f / (accl * accl);
        float invh = 1.0f / (acch * acch);
        s_inv[warp * 16 + g]     = invl;
        s_inv[warp * 16 + g + 8] = invh;
        inv_d2[slice * NN + row_lo] = invl;
        inv_d2[slice * NN + row_hi] = invh;
    }
    __syncthreads();

    // wl epilogue: this block's 128 nodes, two adjacent nodes per iteration,
    // packed into scaled fp16x2; layout [chunk16][lane][nb][h].
#pragma unroll 2
    for (int t = 0; t < 16; t += 2) {
        int nl  = warp * 16 + t;
        int j11 = iblk * 128 + nl;                 // even
        size_t gj = (size_t)slice * NN + j11;
        float wv0 = w[gj * IW + lane];
        float wv1 = w[(gj + 1) * IW + lane];
        float acc0 = 0.0f, acc1 = 0.0f;
#pragma unroll
        for (int k = 0; k < IW; k++) {
            float lwk = lw[lane * 33 + k];
            acc0 = fmaf(__shfl_sync(0xffffffffu, wv0, k), lwk, acc0);
            acc1 = fmaf(__shfl_sync(0xffffffffu, wv1, k), lwk, acc1);
        }
        acc0 *= s_inv[nl] * WLSCALE;
        acc1 *= s_inv[nl + 1] * WLSCALE;
        unsigned pk = pack_f16(acc0, acc1);        // lo = even j

        // lane here is the output channel o; target fragment position:
        int chunk16 = j11 >> 4;
        int kk      = j11 & 15;                    // even
        int tg_d    = (kk >> 1) & 3;
        int h       = kk >> 3;
        int nb_d    = lane >> 3;                   // o octet
        int g_d     = lane & 7;                    // n within octet
        int tlane   = g_d * 4 + tg_d;              // reading lane in main
        size_t addr = (((size_t)slice * 128 + chunk16) * 32 + tlane) * 8
                    + nb_d * 2 + h;
        wlh[addr] = pk;
    }
}

// ---------------------------------------------------------------------------
// Pass C (hot): fp32-FFMA distances + fp16 m16n8k16 product MMAs.
// smem: ps (32KB float4) | wls[2][2048] u32 (16KB) = 48KB.
// Single __syncthreads per 128-j tile, cp.async double buffer.
// ---------------------------------------------------------------------------
#define JTILE   128
#define NTILES  (NN / JTILE)

__global__ void __launch_bounds__(256) main_kernel(
    const float* __restrict__ pos, const unsigned* __restrict__ wlh,
    const float* __restrict__ inv_d2, const float* __restrict__ lin_b,
    float* __restrict__ out) {
    __shared__ float4   ps[NN];          // 32 KB
    __shared__ unsigned wls[2][2048];    // 2 x 8 KB

    int slice = blockIdx.x >> 4;
    int iblk  = blockIdx.x & 15;
    const float* p = pos + (size_t)slice * NN * 3;
    int tid = threadIdx.x;

    for (int n = tid; n < NN; n += 256) {
        float x = p[3 * n + 0], y = p[3 * n + 1], z = p[3 * n + 2];
        ps[n] = make_float4(x, y, z, C1 * (x * x + y * y + z * z));
    }

    int warp = tid >> 5;
    int lane = tid & 31;
    int g = lane >> 2, tg = lane & 3;
    int row_lo = iblk * 128 + warp * 16 + g;
    int row_hi = row_lo + 8;

    float qxl, qyl, qzl, csl, qxh, qyh, qzh, csh;
    {
        float x = p[3 * row_lo], y = p[3 * row_lo + 1], z = p[3 * row_lo + 2];
        csl = C1 * (x * x + y * y + z * z);
        qxl = M2C1 * x; qyl = M2C1 * y; qzl = M2C1 * z;
        x = p[3 * row_hi]; y = p[3 * row_hi + 1]; z = p[3 * row_hi + 2];
        csh = C1 * (x * x + y * y + z * z);
        qxh = M2C1 * x; qyh = M2C1 * y; qzh = M2C1 * z;
    }

    // wl source for this slice: 2048 u32 per 128-j tile
    const unsigned* wsrc = wlh + (size_t)slice * 32768;
    uint32_t wls_sm = (uint32_t)__cvta_generic_to_shared(&wls[0][0]);

    // prologue: tile 0 -> buffer 0 (256 thr x 2 x 16B = 8KB)
    {
        const uint4* src = (const uint4*)wsrc;
        cp_async16(wls_sm + tid * 16, src + tid);
        cp_async16(wls_sm + 4096 + tid * 16, src + tid + 256);
        asm volatile("cp.async.commit_group;");
    }

    float acc[16];
#pragma unroll
    for (int r = 0; r < 16; r++) acc[r] = 0.0f;

    for (int tile = 0; tile < NTILES; tile++) {
        int cur = tile & 1;
        asm volatile("cp.async.wait_group 0;");
        __syncthreads();   // buffer cur filled + everyone done with cur^1

        if (tile + 1 < NTILES) {
            const uint4* src = (const uint4*)(wsrc + (tile + 1) * 2048);
            uint32_t d = wls_sm + (cur ^ 1) * 8192 + tid * 16;
            cp_async16(d, src + tid);
            cp_async16(d + 4096, src + tid + 256);
            asm volatile("cp.async.commit_group;");
        }

        const unsigned* wbuf = wls[cur];
#pragma unroll
        for (int cc = 0; cc < JTILE / 16; cc++) {
            int jb = tile * JTILE + cc * 16;
            int j0 = jb + 2 * tg;       // k = 2tg
            float4 pj0 = ps[j0];
            float4 pj1 = ps[j0 + 1];    // k = 2tg+1
            float4 pj2 = ps[j0 + 8];    // k = 2tg+8
            float4 pj3 = ps[j0 + 9];    // k = 2tg+9

            float tl0 = csl + pj0.w;
            tl0 = fmaf(qxl, pj0.x, tl0); tl0 = fmaf(qyl, pj0.y, tl0); tl0 = fmaf(qzl, pj0.z, tl0);
            float tl1 = csl + pj1.w;
            tl1 = fmaf(qxl, pj1.x, tl1); tl1 = fmaf(qyl, pj1.y, tl1); tl1 = fmaf(qzl, pj1.z, tl1);
            float tl2 = csl + pj2.w;
            tl2 = fmaf(qxl, pj2.x, tl2); tl2 = fmaf(qyl, pj2.y, tl2); tl2 = fmaf(qzl, pj2.z, tl2);
            float tl3 = csl + pj3.w;
            tl3 = fmaf(qxl, pj3.x, tl3); tl3 = fmaf(qyl, pj3.y, tl3); tl3 = fmaf(qzl, pj3.z, tl3);

            float th0 = csh + pj0.w;
            th0 = fmaf(qxh, pj0.x, th0); th0 = fmaf(qyh, pj0.y, th0); th0 = fmaf(qzh, pj0.z, th0);
            float th1 = csh + pj1.w;
            th1 = fmaf(qxh, pj1.x, th1); th1 = fmaf(qyh, pj1.y, th1); th1 = fmaf(qzh, pj1.z, th1);
            float th2 = csh + pj2.w;
            th2 = fmaf(qxh, pj2.x, th2); th2 = fmaf(qyh, pj2.y, th2); th2 = fmaf(qzh, pj2.z, th2);
            float th3 = csh + pj3.w;
            th3 = fmaf(qxh, pj3.x, th3); th3 = fmaf(qyh, pj3.y, th3); th3 = fmaf(qzh, pj3.z, th3);

            unsigned a0 = pack_f16(ex2f(tl0), ex2f(tl1));  // row_lo, k=2tg,2tg+1
            unsigned a1 = pack_f16(ex2f(th0), ex2f(th1));  // row_hi
            unsigned a2 = pack_f16(ex2f(tl2), ex2f(tl3));  // row_lo, k=+8
            unsigned a3 = pack_f16(ex2f(th2), ex2f(th3));  // row_hi

            // b fragments: 8 contiguous u32 per lane -> 2 x LDS.128
            const unsigned* bb = wbuf + cc * 256 + lane * 8;
            uint4 b01 = *(const uint4*)bb;        // nb0:{b0,b1}, nb1:{b0,b1}
            uint4 b23 = *(const uint4*)(bb + 4);  // nb2, nb3

            mma_f16(acc + 0,  a0, a1, a2, a3, b01.x, b01.y);
            mma_f16(acc + 4,  a0, a1, a2, a3, b01.z, b01.w);
            mma_f16(acc + 8,  a0, a1, a2, a3, b23.x, b23.y);
            mma_f16(acc + 12, a0, a1, a2, a3, b23.z, b23.w);
        }
    }

    float invl = inv_d2[slice * NN + row_lo] * INV_WLSCALE;
    float invh = inv_d2[slice * NN + row_hi] * INV_WLSCALE;
    float* orow_lo = out + ((size_t)slice * NN + row_lo) * OW;
    float* orow_hi = out + ((size_t)slice * NN + row_hi) * OW;
#pragma unroll
    for (int nb = 0; nb < 4; nb++) {
        int col = nb * 8 + tg * 2;
        float lb0 = __ldg(lin_b + col);
        float lb1 = __ldg(lin_b + col + 1);
        float2 vlo = make_float2(fmaf(acc[nb * 4 + 0], invl, lb0),
                                 fmaf(acc[nb * 4 + 1], invl, lb1));
        float2 vhi = make_float2(fmaf(acc[nb * 4 + 2], invh, lb0),
                                 fmaf(acc[nb * 4 + 3], invh, lb1));
        *(float2*)(orow_lo + col) = vlo;
        *(float2*)(orow_hi + col) = vhi;
    }
}

// ---------------------------------------------------------------------------
// Launcher
// ---------------------------------------------------------------------------
extern "C" void kernel_launch(void* const* d_in, const int* in_sizes, int n_in,
                              void* d_out, int out_size) {
    const float* positions = (const float*)d_in[0];
    const float* weights   = (const float*)d_in[1];
    const float* lin_w     = (const float*)d_in[2];
    const float* lin_b     = (const float*)d_in[3];
    float* out = (float*)d_out;

    int pos_elems = in_sizes[0];
    float* out_weights = out + pos_elems;

    float* inv_d2;
    unsigned* wlh;
    cudaGetSymbolAddress((void**)&inv_d2, g_inv_d2);
    cudaGetSymbolAddress((void**)&wlh, g_wlh);

    cudaMemcpyAsync(out, positions, (size_t)pos_elems * sizeof(float),
                    cudaMemcpyDeviceToDevice);

    deg_wl_kernel<<<NSLICE * 16, 256>>>(positions, weights, lin_w, inv_d2, wlh);
    main_kernel<<<NSLICE * 16, 256>>>(positions, wlh, inv_d2, lin_b, out_weights);
}

// round 9
// speedup vs baseline: 1.1413x; 1.1413x over previous
#include <cuda_runtime.h>
#include <cstdint>

// Problem constants.
#define NSLICE 32      // B*KI = 8*4
#define NN     2048    // nodes per slice
#define IW     32
#define OW     32

// exp(-sq/2) = exp2(C1 * sq), C1 = -1/(2 ln 2)
#define C1   (-0.7213475204444817f)
#define M2C1 ( 1.4426950408889634f)   // -2*C1
#define WLSCALE    4096.0f
#define INV_WLSCALE (1.0f / 4096.0f)

// Scratch (device globals: allocation-free contract).
__device__ float g_inv_d2[NSLICE * NN];
// wl as packed fp16x2 (scaled by WLSCALE) in m16n8k16 B-fragment order:
// [slice][chunk16(128)][nb(4)][lane(32)][h(2)]
__device__ unsigned g_wlh[(size_t)NSLICE * 128 * 4 * 64];

// ---------------------------------------------------------------------------
// PTX helpers
// ---------------------------------------------------------------------------
__device__ __forceinline__ float ex2f(float x) {
    float y; asm("ex2.approx.f32 %0, %1;" : "=f"(y) : "f"(x)); return y;
}
__device__ __forceinline__ unsigned cvt_tf32(float x) {
    unsigned y; asm("cvt.rna.tf32.f32 %0, %1;" : "=r"(y) : "f"(x)); return y;
}
__device__ __forceinline__ unsigned pack_f16(float lo, float hi) {
    unsigned d;
    asm("cvt.rn.f16x2.f32 %0, %1, %2;" : "=r"(d) : "f"(hi), "f"(lo));
    return d;
}
// geometry MMA with separate C (init form): D = A(16x4)*B(4x8) + C
__device__ __forceinline__ void mma_k4_init(
    float& d0, float& d1, float& d2, float& d3,
    unsigned a0, unsigned a1, unsigned b0,
    float c0, float c1, float c2, float c3) {
    asm volatile(
        "mma.sync.aligned.m16n8k4.row.col.f32.tf32.tf32.f32 "
        "{%0,%1,%2,%3}, {%4,%5}, {%6}, {%7,%8,%9,%10};"
        : "=f"(d0), "=f"(d1), "=f"(d2), "=f"(d3)
        : "r"(a0), "r"(a1), "r"(b0), "f"(c0), "f"(c1), "f"(c2), "f"(c3));
}
// geometry MMA accumulate form
__device__ __forceinline__ void mma_k4(float& c0, float& c1, float& c2, float& c3,
                                       unsigned a0, unsigned a1, unsigned b0) {
    asm volatile(
        "mma.sync.aligned.m16n8k4.row.col.f32.tf32.tf32.f32 "
        "{%0,%1,%2,%3}, {%4,%5}, {%6}, {%0,%1,%2,%3};"
        : "+f"(c0), "+f"(c1), "+f"(c2), "+f"(c3)
        : "r"(a0), "r"(a1), "r"(b0));
}
// product MMA: C += A(16x16) * B(16x8), fp16 -> fp32
__device__ __forceinline__ void mma_f16(float* c, unsigned a0, unsigned a1,
                                        unsigned a2, unsigned a3,
                                        unsigned b0, unsigned b1) {
    asm volatile(
        "mma.sync.aligned.m16n8k16.row.col.f32.f16.f16.f32 "
        "{%0,%1,%2,%3}, {%4,%5,%6,%7}, {%8,%9}, {%0,%1,%2,%3};"
        : "+f"(c[0]), "+f"(c[1]), "+f"(c[2]), "+f"(c[3])
        : "r"(a0), "r"(a1), "r"(a2), "r"(a3), "r"(b0), "r"(b1));
}
__device__ __forceinline__ void cp_async16(uint32_t dst, const void* src) {
    asm volatile("cp.async.cg.shared.global [%0], [%1], 16;" :: "r"(dst), "l"(src));
}

// ---------------------------------------------------------------------------
// Pass A (fused): degrees via COMPENSATED (tf32x3-style) geometry MMA:
// t = cs_i + Ah*Bh + Ah*Bl + Al*Bh, with cs_j (hi+lo) folded into k=3.
// Per-pair error ~2^-24 -> d_i accurate to ~1e-6. Then wl epilogue.
// 256 blocks x 512 thr; block owns 256 rows; single wave on 148 SMs.
// Dyn smem: vg_hi[256][4][8] | vg_lo[256][4][8]  (64 KB)
// ---------------------------------------------------------------------------
extern __shared__ float dsm[];

__global__ void __launch_bounds__(512) deg_wl_kernel(
    const float* __restrict__ pos, const float* __restrict__ w,
    const float* __restrict__ lin_w, float* __restrict__ inv_d2,
    unsigned* __restrict__ wlh) {
    float* vg_hi = dsm;          // 8192 floats
    float* vg_lo = dsm + 8192;   // 8192 floats
    __shared__ float s_inv[256];
    __shared__ float lw[OW * 33];

    int slice = blockIdx.x >> 3;
    int iblk  = blockIdx.x & 7;
    const float* p = pos + (size_t)slice * NN * 3;
    int tid = threadIdx.x;

    for (int t = tid; t < OW * IW; t += 512)
        lw[(t >> 5) * 33 + (t & 31)] = lin_w[t];

    for (int n = tid; n < NN; n += 512) {
        float x = p[3 * n + 0], y = p[3 * n + 1], z = p[3 * n + 2];
        float cs = C1 * (x * x + y * y + z * z);
        int c = n >> 3, jn = n & 7;
        int ncol = 2 * (jn & 3) + (jn >> 2);
        int base = c * 32 + ncol;
        unsigned xh = cvt_tf32(x), yh = cvt_tf32(y), zh = cvt_tf32(z);
        unsigned ch = cvt_tf32(cs);
        vg_hi[base + 0 * 8] = __uint_as_float(xh);
        vg_hi[base + 1 * 8] = __uint_as_float(yh);
        vg_hi[base + 2 * 8] = __uint_as_float(zh);
        vg_hi[base + 3 * 8] = __uint_as_float(ch);
        vg_lo[base + 0 * 8] = __uint_as_float(cvt_tf32(x - __uint_as_float(xh)));
        vg_lo[base + 1 * 8] = __uint_as_float(cvt_tf32(y - __uint_as_float(yh)));
        vg_lo[base + 2 * 8] = __uint_as_float(cvt_tf32(z - __uint_as_float(zh)));
        vg_lo[base + 3 * 8] = __uint_as_float(cvt_tf32(cs - __uint_as_float(ch)));
    }

    int warp = tid >> 5;
    int lane = tid & 31;
    int g = lane >> 2, tg = lane & 3;
    int row_lo = iblk * 256 + warp * 16 + g;
    int row_hi = row_lo + 8;

    float csl, csh;
    unsigned ah0, al0, ah1, al1;
    {
        float x = p[3 * row_lo], y = p[3 * row_lo + 1], z = p[3 * row_lo + 2];
        csl = C1 * (x * x + y * y + z * z);
        float comp = (tg == 0) ? x : (tg == 1) ? y : z;
        float q = M2C1 * comp;
        unsigned qh = cvt_tf32(q);
        ah0 = (tg == 3) ? 0x3f800000u : qh;
        al0 = (tg == 3) ? 0u : cvt_tf32(q - __uint_as_float(qh));
        x = p[3 * row_hi]; y = p[3 * row_hi + 1]; z = p[3 * row_hi + 2];
        csh = C1 * (x * x + y * y + z * z);
        comp = (tg == 0) ? x : (tg == 1) ? y : z;
        q = M2C1 * comp;
        qh = cvt_tf32(q);
        ah1 = (tg == 3) ? 0x3f800000u : qh;
        al1 = (tg == 3) ? 0u : cvt_tf32(q - __uint_as_float(qh));
    }
    __syncthreads();

    float a0l = 0.0f, a1l = 0.0f, a0h = 0.0f, a1h = 0.0f;
#pragma unroll 4
    for (int c = 0; c < 256; c++) {
        unsigned bh = __float_as_uint(vg_hi[c * 32 + tg * 8 + g]);
        unsigned bl = __float_as_uint(vg_lo[c * 32 + tg * 8 + g]);
        float t0, t1, t2, t3;
        mma_k4_init(t0, t1, t2, t3, ah0, ah1, bh, csl, csl, csh, csh);
        mma_k4(t0, t1, t2, t3, ah0, ah1, bl);
        mma_k4(t0, t1, t2, t3, al0, al1, bh);
        a0l += ex2f(t0); a1l += ex2f(t1);
        a0h += ex2f(t2); a1h += ex2f(t3);
    }
    float accl = a0l + a1l;
    float acch = a0h + a1h;
    accl += __shfl_xor_sync(0xffffffffu, accl, 1);
    accl += __shfl_xor_sync(0xffffffffu, accl, 2);
    acch += __shfl_xor_sync(0xffffffffu, acch, 1);
    acch += __shfl_xor_sync(0xffffffffu, acch, 2);
    if (tg == 0) {
        float invl = 1.0f / (accl * accl);
        float invh = 1.0f / (acch * acch);
        s_inv[warp * 16 + g]     = invl;
        s_inv[warp * 16 + g + 8] = invh;
        inv_d2[slice * NN + row_lo] = invl;
        inv_d2[slice * NN + row_hi] = invh;
    }
    __syncthreads();

    // wl epilogue: this block's 256 nodes (16 per warp), two per iteration,
    // packed into scaled fp16x2; layout [chunk16][nb][lane][h] (conflict-free).
#pragma unroll 2
    for (int t = 0; t < 16; t += 2) {
        int nl  = warp * 16 + t;
        int j11 = iblk * 256 + nl;                 // even
        size_t gj = (size_t)slice * NN + j11;
        float wv0 = w[gj * IW + lane];
        float wv1 = w[(gj + 1) * IW + lane];
        float acc0 = 0.0f, acc1 = 0.0f;
#pragma unroll
        for (int k = 0; k < IW; k++) {
            float lwk = lw[lane * 33 + k];
            acc0 = fmaf(__shfl_sync(0xffffffffu, wv0, k), lwk, acc0);
            acc1 = fmaf(__shfl_sync(0xffffffffu, wv1, k), lwk, acc1);
        }
        acc0 *= s_inv[nl] * WLSCALE;
        acc1 *= s_inv[nl + 1] * WLSCALE;
        unsigned pk = pack_f16(acc0, acc1);        // lo = even j

        int chunk16 = j11 >> 4;
        int kk      = j11 & 15;                    // even
        int tg_d    = (kk >> 1) & 3;
        int h       = kk >> 3;
        int nb_d    = lane >> 3;                   // o octet
        int g_d     = lane & 7;                    // n within octet
        size_t addr = (((size_t)slice * 128 + chunk16) * 4 + nb_d) * 64
                    + (g_d * 4 + tg_d) * 2 + h;
        wlh[addr] = pk;
    }
}

// ---------------------------------------------------------------------------
// Pass C (hot): fp32-FFMA distances + fp16 m16n8k16 product MMAs.
// (round-7 verified version: conflict-free [nb][lane][h] B layout)
// smem: ps (32KB float4) | wls[2][2048] u32 (16KB) = 48KB.
// ---------------------------------------------------------------------------
#define JTILE   128
#define NTILES  (NN / JTILE)

__global__ void __launch_bounds__(256) main_kernel(
    const float* __restrict__ pos, const unsigned* __restrict__ wlh,
    const float* __restrict__ inv_d2, const float* __restrict__ lin_b,
    float* __restrict__ out) {
    __shared__ float4   ps[NN];          // 32 KB
    __shared__ unsigned wls[2][2048];    // 2 x 8 KB

    int slice = blockIdx.x >> 4;
    int iblk  = blockIdx.x & 15;
    const float* p = pos + (size_t)slice * NN * 3;
    int tid = threadIdx.x;

    for (int n = tid; n < NN; n += 256) {
        float x = p[3 * n + 0], y = p[3 * n + 1], z = p[3 * n + 2];
        ps[n] = make_float4(x, y, z, C1 * (x * x + y * y + z * z));
    }

    int warp = tid >> 5;
    int lane = tid & 31;
    int g = lane >> 2, tg = lane & 3;
    int row_lo = iblk * 128 + warp * 16 + g;
    int row_hi = row_lo + 8;

    float qxl, qyl, qzl, csl, qxh, qyh, qzh, csh;
    {
        float x = p[3 * row_lo], y = p[3 * row_lo + 1], z = p[3 * row_lo + 2];
        csl = C1 * (x * x + y * y + z * z);
        qxl = M2C1 * x; qyl = M2C1 * y; qzl = M2C1 * z;
        x = p[3 * row_hi]; y = p[3 * row_hi + 1]; z = p[3 * row_hi + 2];
        csh = C1 * (x * x + y * y + z * z);
        qxh = M2C1 * x; qyh = M2C1 * y; qzh = M2C1 * z;
    }

    const unsigned* wsrc = wlh + (size_t)slice * 32768;
    uint32_t wls_sm = (uint32_t)__cvta_generic_to_shared(&wls[0][0]);

    // prologue: tile 0 -> buffer 0 (256 thr x 2 x 16B = 8KB)
    {
        const uint4* src = (const uint4*)wsrc;
        cp_async16(wls_sm + tid * 16, src + tid);
        cp_async16(wls_sm + 4096 + tid * 16, src + tid + 256);
        asm volatile("cp.async.commit_group;");
    }

    float acc[16];
#pragma unroll
    for (int r = 0; r < 16; r++) acc[r] = 0.0f;

    for (int tile = 0; tile < NTILES; tile++) {
        int cur = tile & 1;
        asm volatile("cp.async.wait_group 0;");
        __syncthreads();   // buffer cur filled + everyone done with cur^1

        if (tile + 1 < NTILES) {
            const uint4* src = (const uint4*)(wsrc + (tile + 1) * 2048);
            uint32_t d = wls_sm + (cur ^ 1) * 8192 + tid * 16;
            cp_async16(d, src + tid);
            cp_async16(d + 4096, src + tid + 256);
            asm volatile("cp.async.commit_group;");
        }

        const unsigned* wbuf = wls[cur];
#pragma unroll
        for (int cc = 0; cc < JTILE / 16; cc++) {
            int jb = tile * JTILE + cc * 16;
            int j0 = jb + 2 * tg;       // k = 2tg
            float4 pj0 = ps[j0];
            float4 pj1 = ps[j0 + 1];    // k = 2tg+1
            float4 pj2 = ps[j0 + 8];    // k = 2tg+8
            float4 pj3 = ps[j0 + 9];    // k = 2tg+9

            float tl0 = csl + pj0.w;
            tl0 = fmaf(qxl, pj0.x, tl0); tl0 = fmaf(qyl, pj0.y, tl0); tl0 = fmaf(qzl, pj0.z, tl0);
            float tl1 = csl + pj1.w;
            tl1 = fmaf(qxl, pj1.x, tl1); tl1 = fmaf(qyl, pj1.y, tl1); tl1 = fmaf(qzl, pj1.z, tl1);
            float tl2 = csl + pj2.w;
            tl2 = fmaf(qxl, pj2.x, tl2); tl2 = fmaf(qyl, pj2.y, tl2); tl2 = fmaf(qzl, pj2.z, tl2);
            float tl3 = csl + pj3.w;
            tl3 = fmaf(qxl, pj3.x, tl3); tl3 = fmaf(qyl, pj3.y, tl3); tl3 = fmaf(qzl, pj3.z, tl3);

            float th0 = csh + pj0.w;
            th0 = fmaf(qxh, pj0.x, th0); th0 = fmaf(qyh, pj0.y, th0); th0 = fmaf(qzh, pj0.z, th0);
            float th1 = csh + pj1.w;
            th1 = fmaf(qxh, pj1.x, th1); th1 = fmaf(qyh, pj1.y, th1); th1 = fmaf(qzh, pj1.z, th1);
            float th2 = csh + pj2.w;
            th2 = fmaf(qxh, pj2.x, th2); th2 = fmaf(qyh, pj2.y, th2); th2 = fmaf(qzh, pj2.z, th2);
            float th3 = csh + pj3.w;
            th3 = fmaf(qxh, pj3.x, th3); th3 = fmaf(qyh, pj3.y, th3); th3 = fmaf(qzh, pj3.z, th3);

            unsigned a0 = pack_f16(ex2f(tl0), ex2f(tl1));  // row_lo, k=2tg,2tg+1
            unsigned a1 = pack_f16(ex2f(th0), ex2f(th1));  // row_hi
            unsigned a2 = pack_f16(ex2f(tl2), ex2f(tl3));  // row_lo, k=+8
            unsigned a3 = pack_f16(ex2f(th2), ex2f(th3));  // row_hi

#pragma unroll
            for (int nb = 0; nb < 4; nb++) {
                uint2 b = *(const uint2*)(wbuf + (cc * 4 + nb) * 64 + lane * 2);
                mma_f16(acc + nb * 4, a0, a1, a2, a3, b.x, b.y);
            }
        }
    }

    float invl = inv_d2[slice * NN + row_lo] * INV_WLSCALE;
    float invh = inv_d2[slice * NN + row_hi] * INV_WLSCALE;
    float* orow_lo = out + ((size_t)slice * NN + row_lo) * OW;
    float* orow_hi = out + ((size_t)slice * NN + row_hi) * OW;
#pragma unroll
    for (int nb = 0; nb < 4; nb++) {
        int col = nb * 8 + tg * 2;
        float lb0 = __ldg(lin_b + col);
        float lb1 = __ldg(lin_b + col + 1);
        float2 vlo = make_float2(fmaf(acc[nb * 4 + 0], invl, lb0),
                                 fmaf(acc[nb * 4 + 1], invl, lb1));
        float2 vhi = make_float2(fmaf(acc[nb * 4 + 2], invh, lb0),
                                 fmaf(acc[nb * 4 + 3], invh, lb1));
        *(float2*)(orow_lo + col) = vlo;
        *(float2*)(orow_hi + col) = vhi;
    }
}

// ---------------------------------------------------------------------------
// Launcher
// ---------------------------------------------------------------------------
extern "C" void kernel_launch(void* const* d_in, const int* in_sizes, int n_in,
                              void* d_out, int out_size) {
    const float* positions = (const float*)d_in[0];
    const float* weights   = (const float*)d_in[1];
    const float* lin_w     = (const float*)d_in[2];
    const float* lin_b     = (const float*)d_in[3];
    float* out = (float*)d_out;

    int pos_elems = in_sizes[0];
    float* out_weights = out + pos_elems;

    float* inv_d2;
    unsigned* wlh;
    cudaGetSymbolAddress((void**)&inv_d2, g_inv_d2);
    cudaGetSymbolAddress((void**)&wlh, g_wlh);

    cudaFuncSetAttribute(deg_wl_kernel,
                         cudaFuncAttributeMaxDynamicSharedMemorySize, 65536);

    cudaMemcpyAsync(out, positions, (size_t)pos_elems * sizeof(float),
                    cudaMemcpyDeviceToDevice);

    deg_wl_kernel<<<NSLICE * 8, 512, 65536>>>(positions, weights, lin_w,
                                              inv_d2, wlh);
    main_kernel<<<NSLICE * 16, 256>>>(positions, wlh, inv_d2, lin_b, out_weights);
}

// round 10
// speedup vs baseline: 1.2590x; 1.1032x over previous
#include <cuda_runtime.h>
#include <cuda_fp16.h>
#include <cstdint>

// Problem constants.
#define NSLICE 32      // B*KI = 8*4
#define NN     2048    // nodes per slice
#define IW     32
#define OW     32

// exp(-sq/2) = exp2(C1 * sq), C1 = -1/(2 ln 2)
#define C1   (-0.7213475204444817f)
#define M2C1 ( 1.4426950408889634f)   // -2*C1
#define WLSCALE    4096.0f
#define INV_WLSCALE (1.0f / 4096.0f)

// Scratch (device globals: allocation-free contract).
__device__ float g_inv_d2[NSLICE * NN];
// wl as packed fp16x2 (scaled by WLSCALE) in m16n8k16 B-fragment order:
// [slice][chunk16(128)][nb(4)][lane(32)][h(2)]
__device__ unsigned g_wlh[(size_t)NSLICE * 128 * 4 * 64];

// ---------------------------------------------------------------------------
// PTX helpers
// ---------------------------------------------------------------------------
__device__ __forceinline__ float ex2f(float x) {
    float y; asm("ex2.approx.f32 %0, %1;" : "=f"(y) : "f"(x)); return y;
}
__device__ __forceinline__ unsigned pack_f16(float lo, float hi) {
    unsigned d;
    asm("cvt.rn.f16x2.f32 %0, %1, %2;" : "=r"(d) : "f"(hi), "f"(lo));
    return d;
}
__device__ __forceinline__ unsigned pack2h(__half lo, __half hi) {
    return ((unsigned)__half_as_ushort(hi) << 16) | __half_as_ushort(lo);
}
// product/geometry MMA accumulate form: C += A(16x16)*B(16x8), fp16 -> fp32
__device__ __forceinline__ void mma_f16(float* c, unsigned a0, unsigned a1,
                                        unsigned a2, unsigned a3,
                                        unsigned b0, unsigned b1) {
    asm volatile(
        "mma.sync.aligned.m16n8k16.row.col.f32.f16.f16.f32 "
        "{%0,%1,%2,%3}, {%4,%5,%6,%7}, {%8,%9}, {%0,%1,%2,%3};"
        : "+f"(c[0]), "+f"(c[1]), "+f"(c[2]), "+f"(c[3])
        : "r"(a0), "r"(a1), "r"(a2), "r"(a3), "r"(b0), "r"(b1));
}
// geometry MMA with separate C (init form): D = A*B + C
__device__ __forceinline__ void mma_f16_init(
    float& d0, float& d1, float& d2, float& d3,
    unsigned a0, unsigned a1, unsigned a2, unsigned a3,
    unsigned b0, unsigned b1,
    float c0, float c1, float c2, float c3) {
    asm volatile(
        "mma.sync.aligned.m16n8k16.row.col.f32.f16.f16.f32 "
        "{%0,%1,%2,%3}, {%4,%5,%6,%7}, {%8,%9}, {%10,%11,%12,%13};"
        : "=f"(d0), "=f"(d1), "=f"(d2), "=f"(d3)
        : "r"(a0), "r"(a1), "r"(a2), "r"(a3), "r"(b0), "r"(b1),
          "f"(c0), "f"(c1), "f"(c2), "f"(c3));
}
__device__ __forceinline__ void cp_async16(uint32_t dst, const void* src) {
    asm volatile("cp.async.cg.shared.global [%0], [%1], 16;" :: "r"(dst), "l"(src));
}

// ---------------------------------------------------------------------------
// Geometry staging: per node j, fp16 two-term splits packed as 4 u32 pairs:
//  pair0 = (xh, yh), pair1 = (zh, csh), pair2 = (xl, yl), pair3 = (zl, csl)
// layout geom[oct(256)][pair(4)][j8(8)] -> 32 u32 per octet (32 KB total).
// ---------------------------------------------------------------------------
__device__ __forceinline__ void stage_geom(const float* __restrict__ p,
                                           unsigned* geom, int tid, int nt) {
    for (int n = tid; n < NN; n += nt) {
        float x = p[3 * n + 0], y = p[3 * n + 1], z = p[3 * n + 2];
        float cs = C1 * (x * x + y * y + z * z);
        __half xh = __float2half_rn(x), yh = __float2half_rn(y);
        __half zh = __float2half_rn(z), ch = __float2half_rn(cs);
        float xl = x - __half2float(xh), yl = y - __half2float(yh);
        float zl = z - __half2float(zh), cl = cs - __half2float(ch);
        int base = ((n >> 3) << 5) + (n & 7);
        geom[base + 0]  = pack2h(xh, yh);
        geom[base + 8]  = pack2h(zh, ch);
        geom[base + 16] = pack_f16(xl, yl);
        geom[base + 24] = pack_f16(zl, cl);
    }
}

// Row-side A-fragment component for this thread's tg slot.
// A k-layout: k0-3={qxh,qyh,qzh,1}, k4-7={qxl,qyl,qzl,1},
//             k8-11={qxh,qyh,qzh,0}, k12-15={qxl,qyl,qzl,0}
// a(tg) covers k = 2tg, 2tg+1; the k+8 variant = same with hi-half zeroed (tg odd).
__device__ __forceinline__ unsigned make_afrag(float x, float y, float z, int tg) {
    float qx = M2C1 * x, qy = M2C1 * y, qz = M2C1 * z;
    __half qxh = __float2half_rn(qx), qyh = __float2half_rn(qy);
    __half qzh = __float2half_rn(qz);
    if (tg == 0) return pack2h(qxh, qyh);
    if (tg == 1) return pack2h(qzh, __float2half_rn(1.0f));
    float qxl = qx - __half2float(qxh), qyl = qy - __half2float(qyh);
    float qzl = qz - __half2float(qzh);
    if (tg == 2) return pack_f16(qxl, qyl);
    return pack_f16(qzl, 1.0f);
}

// Per-octet geometry B-fragment from packed pairs.
__device__ __forceinline__ void geom_bfrag(const unsigned* geom, int oct, int off,
                                           unsigned is3, unsigned odd,
                                           unsigned& b0, unsigned& b1) {
    unsigned pa = geom[oct * 32 + off];        // pair0 or pair1
    unsigned pb = geom[oct * 32 + 16 + off];   // pair2 or pair3
    b0 = is3 ? __byte_perm(pa, pb, 0x7610) : pa;   // tg3: (zh, csl)
    b1 = odd ? (pb & 0x0000FFFFu) : pb;            // odd tg: zero hi (cs slot)
}

// ---------------------------------------------------------------------------
// Pass A (fused): degrees via split-fp16 geometry MMA (1 MMA per 16 rows x 8 j,
// fp32-accurate: fp16 products are exact, residual ~2^-22), then wl epilogue.
// 256 blocks x 512 thr; block owns 256 rows.
// ---------------------------------------------------------------------------
__global__ void __launch_bounds__(512) deg_wl_kernel(
    const float* __restrict__ pos, const float* __restrict__ w,
    const float* __restrict__ lin_w, float* __restrict__ inv_d2,
    unsigned* __restrict__ wlh) {
    __shared__ unsigned geom[256 * 32];   // 32 KB
    __shared__ float s_inv[256];
    __shared__ float lw[OW * 33];

    int slice = blockIdx.x >> 3;
    int iblk  = blockIdx.x & 7;
    const float* p = pos + (size_t)slice * NN * 3;
    int tid = threadIdx.x;

    for (int t = tid; t < OW * IW; t += 512)
        lw[(t >> 5) * 33 + (t & 31)] = lin_w[t];

    stage_geom(p, geom, tid, 512);

    int warp = tid >> 5;
    int lane = tid & 31;
    int g = lane >> 2, tg = lane & 3;
    unsigned odd = tg & 1, is3 = (tg == 3);
    int off = (tg & 1) * 8 + g;
    int row_lo = iblk * 256 + warp * 16 + g;
    int row_hi = row_lo + 8;

    float csl, csh;
    unsigned afl, afh, aflm, afhm;
    {
        float x = p[3 * row_lo], y = p[3 * row_lo + 1], z = p[3 * row_lo + 2];
        csl = C1 * (x * x + y * y + z * z);
        afl = make_afrag(x, y, z, tg);
        x = p[3 * row_hi]; y = p[3 * row_hi + 1]; z = p[3 * row_hi + 2];
        csh = C1 * (x * x + y * y + z * z);
        afh = make_afrag(x, y, z, tg);
        aflm = odd ? (afl & 0x0000FFFFu) : afl;
        afhm = odd ? (afh & 0x0000FFFFu) : afh;
    }
    __syncthreads();

    float a0l = 0.0f, a1l = 0.0f, a0h = 0.0f, a1h = 0.0f;
#pragma unroll 4
    for (int oct = 0; oct < 256; oct++) {
        unsigned b0, b1;
        geom_bfrag(geom, oct, off, is3, odd, b0, b1);
        float t0, t1, t2, t3;
        mma_f16_init(t0, t1, t2, t3, afl, afh, aflm, afhm, b0, b1,
                     csl, csl, csh, csh);
        a0l += ex2f(t0); a1l += ex2f(t1);
        a0h += ex2f(t2); a1h += ex2f(t3);
    }
    float accl = a0l + a1l;
    float acch = a0h + a1h;
    accl += __shfl_xor_sync(0xffffffffu, accl, 1);
    accl += __shfl_xor_sync(0xffffffffu, accl, 2);
    acch += __shfl_xor_sync(0xffffffffu, acch, 1);
    acch += __shfl_xor_sync(0xffffffffu, acch, 2);
    if (tg == 0) {
        float invl = 1.0f / (accl * accl);
        float invh = 1.0f / (acch * acch);
        s_inv[warp * 16 + g]     = invl;
        s_inv[warp * 16 + g + 8] = invh;
        inv_d2[slice * NN + row_lo] = invl;
        inv_d2[slice * NN + row_hi] = invh;
    }
    __syncthreads();

    // wl epilogue: this block's 256 nodes (16 per warp), two per iteration,
    // packed into scaled fp16x2; layout [chunk16][nb][lane][h].
#pragma unroll 2
    for (int t = 0; t < 16; t += 2) {
        int nl  = warp * 16 + t;
        int j11 = iblk * 256 + nl;                 // even
        size_t gj = (size_t)slice * NN + j11;
        float wv0 = w[gj * IW + lane];
        float wv1 = w[(gj + 1) * IW + lane];
        float acc0 = 0.0f, acc1 = 0.0f;
#pragma unroll
        for (int k = 0; k < IW; k++) {
            float lwk = lw[lane * 33 + k];
            acc0 = fmaf(__shfl_sync(0xffffffffu, wv0, k), lwk, acc0);
            acc1 = fmaf(__shfl_sync(0xffffffffu, wv1, k), lwk, acc1);
        }
        acc0 *= s_inv[nl] * WLSCALE;
        acc1 *= s_inv[nl + 1] * WLSCALE;
        unsigned pk = pack_f16(acc0, acc1);        // lo = even j

        int chunk16 = j11 >> 4;
        int kk      = j11 & 15;                    // even
        int tg_d    = (kk >> 1) & 3;
        int h       = kk >> 3;
        int nb_d    = lane >> 3;                   // o octet
        int g_d     = lane & 7;                    // n within octet
        size_t addr = (((size_t)slice * 128 + chunk16) * 4 + nb_d) * 64
                    + (g_d * 4 + tg_d) * 2 + h;
        wlh[addr] = pk;
    }
}

// ---------------------------------------------------------------------------
// Pass C (hot): split-fp16 geometry MMA (distances) + fp16 product MMAs.
// smem: geom (32KB) | wls[2][2048] u32 (16KB) = 48KB -> 4 blocks/SM.
// ---------------------------------------------------------------------------
#define JTILE   128
#define NTILES  (NN / JTILE)

__global__ void __launch_bounds__(256) main_kernel(
    const float* __restrict__ pos, const unsigned* __restrict__ wlh,
    const float* __restrict__ inv_d2, const float* __restrict__ lin_b,
    float* __restrict__ out) {
    __shared__ unsigned geom[256 * 32];  // 32 KB
    __shared__ unsigned wls[2][2048];    // 2 x 8 KB

    int slice = blockIdx.x >> 4;
    int iblk  = blockIdx.x & 15;
    const float* p = pos + (size_t)slice * NN * 3;
    int tid = threadIdx.x;

    stage_geom(p, geom, tid, 256);

    int warp = tid >> 5;
    int lane = tid & 31;
    int g = lane >> 2, tg = lane & 3;
    unsigned odd = tg & 1, is3 = (tg == 3);
    int off = (tg & 1) * 8 + g;
    int row_lo = iblk * 128 + warp * 16 + g;
    int row_hi = row_lo + 8;

    float csl, csh;
    unsigned afl, afh, aflm, afhm;
    {
        float x = p[3 * row_lo], y = p[3 * row_lo + 1], z = p[3 * row_lo + 2];
        csl = C1 * (x * x + y * y + z * z);
        afl = make_afrag(x, y, z, tg);
        x = p[3 * row_hi]; y = p[3 * row_hi + 1]; z = p[3 * row_hi + 2];
        csh = C1 * (x * x + y * y + z * z);
        afh = make_afrag(x, y, z, tg);
        aflm = odd ? (afl & 0x0000FFFFu) : afl;
        afhm = odd ? (afh & 0x0000FFFFu) : afh;
    }

    const unsigned* wsrc = wlh + (size_t)slice * 32768;
    uint32_t wls_sm = (uint32_t)__cvta_generic_to_shared(&wls[0][0]);

    // prologue: tile 0 -> buffer 0 (256 thr x 2 x 16B = 8KB)
    {
        const uint4* src = (const uint4*)wsrc;
        cp_async16(wls_sm + tid * 16, src + tid);
        cp_async16(wls_sm + 4096 + tid * 16, src + tid + 256);
        asm volatile("cp.async.commit_group;");
    }

    float acc[16];
#pragma unroll
    for (int r = 0; r < 16; r++) acc[r] = 0.0f;

    for (int tile = 0; tile < NTILES; tile++) {
        int cur = tile & 1;
        asm volatile("cp.async.wait_group 0;");
        __syncthreads();   // buffer cur filled + geom staged (first iter)

        if (tile + 1 < NTILES) {
            const uint4* src = (const uint4*)(wsrc + (tile + 1) * 2048);
            uint32_t d = wls_sm + (cur ^ 1) * 8192 + tid * 16;
            cp_async16(d, src + tid);
            cp_async16(d + 4096, src + tid + 256);
            asm volatile("cp.async.commit_group;");
        }

        const unsigned* wbuf = wls[cur];
#pragma unroll
        for (int cc = 0; cc < JTILE / 16; cc++) {
            int oct0 = tile * (JTILE / 8) + 2 * cc;

            unsigned b0, b1;
            geom_bfrag(geom, oct0, off, is3, odd, b0, b1);
            float t0, t1, t2, t3;
            mma_f16_init(t0, t1, t2, t3, afl, afh, aflm, afhm, b0, b1,
                         csl, csl, csh, csh);

            geom_bfrag(geom, oct0 + 1, off, is3, odd, b0, b1);
            float u0, u1, u2, u3;
            mma_f16_init(u0, u1, u2, u3, afl, afh, aflm, afhm, b0, b1,
                         csl, csl, csh, csh);

            // product A-frags: geometry C layout == product A layout
            unsigned a0 = pack_f16(ex2f(t0), ex2f(t1));  // row_lo, k=2tg,2tg+1
            unsigned a1 = pack_f16(ex2f(t2), ex2f(t3));  // row_hi
            unsigned a2 = pack_f16(ex2f(u0), ex2f(u1));  // row_lo, k=+8
            unsigned a3 = pack_f16(ex2f(u2), ex2f(u3));  // row_hi

#pragma unroll
            for (int nb = 0; nb < 4; nb++) {
                uint2 b = *(const uint2*)(wbuf + (cc * 4 + nb) * 64 + lane * 2);
                mma_f16(acc + nb * 4, a0, a1, a2, a3, b.x, b.y);
            }
        }
    }

    float invl = inv_d2[slice * NN + row_lo] * INV_WLSCALE;
    float invh = inv_d2[slice * NN + row_hi] * INV_WLSCALE;
    float* orow_lo = out + ((size_t)slice * NN + row_lo) * OW;
    float* orow_hi = out + ((size_t)slice * NN + row_hi) * OW;
#pragma unroll
    for (int nb = 0; nb < 4; nb++) {
        int col = nb * 8 + tg * 2;
        float lb0 = __ldg(lin_b + col);
        float lb1 = __ldg(lin_b + col + 1);
        float2 vlo = make_float2(fmaf(acc[nb * 4 + 0], invl, lb0),
                                 fmaf(acc[nb * 4 + 1], invl, lb1));
        float2 vhi = make_float2(fmaf(acc[nb * 4 + 2], invh, lb0),
                                 fmaf(acc[nb * 4 + 3], invh, lb1));
        *(float2*)(orow_lo + col) = vlo;
        *(float2*)(orow_hi + col) = vhi;
    }
}

// ---------------------------------------------------------------------------
// Launcher
// ---------------------------------------------------------------------------
extern "C" void kernel_launch(void* const* d_in, const int* in_sizes, int n_in,
                              void* d_out, int out_size) {
    const float* positions = (const float*)d_in[0];
    const float* weights   = (const float*)d_in[1];
    const float* lin_w     = (const float*)d_in[2];
    const float* lin_b     = (const float*)d_in[3];
    float* out = (float*)d_out;

    int pos_elems = in_sizes[0];
    float* out_weights = out + pos_elems;

    float* inv_d2;
    unsigned* wlh;
    cudaGetSymbolAddress((void**)&inv_d2, g_inv_d2);
    cudaGetSymbolAddress((void**)&wlh, g_wlh);

    cudaMemcpyAsync(out, positions, (size_t)pos_elems * sizeof(float),
                    cudaMemcpyDeviceToDevice);

    deg_wl_kernel<<<NSLICE * 8, 512>>>(positions, weights, lin_w, inv_d2, wlh);
    main_kernel<<<NSLICE * 16, 256>>>(positions, wlh, inv_d2, lin_b, out_weights);
}